// round 8
// baseline (speedup 1.0000x reference)
#include <cuda_runtime.h>
#include <cuda_bf16.h>
#include <cstdint>

#define TS   3584
#define DIM  1536
#define NH   12
#define HD   128
#define VS   1792
#define TPF  448
#define NW   28
#define EPS  1e-6f
#define SCALE 0.08838834764831845f   // 1/sqrt(128)

// -------- scratch (device globals; no allocations allowed) --------
__device__ float g_q[(size_t)TS * DIM];
__device__ float g_k[(size_t)TS * DIM];
__device__ __nv_bfloat16 g_xh[(size_t)TS * DIM];
__device__ __nv_bfloat16 g_xl[(size_t)TS * DIM];
__device__ __nv_bfloat16 g_qh[(size_t)TS * DIM];
__device__ __nv_bfloat16 g_ql[(size_t)TS * DIM];
__device__ __nv_bfloat16 g_kh[(size_t)TS * DIM];
__device__ __nv_bfloat16 g_kl[(size_t)TS * DIM];
__device__ __nv_bfloat16 g_vh[(size_t)TS * DIM];
__device__ __nv_bfloat16 g_vl[(size_t)TS * DIM];
__device__ __nv_bfloat16 g_oh[(size_t)TS * DIM];
__device__ __nv_bfloat16 g_ol[(size_t)TS * DIM];
__device__ __nv_bfloat16 g_wh[4][(size_t)DIM * DIM];
__device__ __nv_bfloat16 g_wl[4][(size_t)DIM * DIM];

// ======================= PTX helpers =======================
__device__ __forceinline__ uint32_t s2u(const void* p) {
    uint32_t a;
    asm("{ .reg .u64 t; cvta.to.shared.u64 t, %1; cvt.u32.u64 %0, t; }"
        : "=r"(a) : "l"(p));
    return a;
}
__device__ __forceinline__ void ldsm_x4(uint32_t* r, uint32_t addr) {
    asm volatile("ldmatrix.sync.aligned.m8n8.x4.shared.b16 {%0,%1,%2,%3}, [%4];"
                 : "=r"(r[0]), "=r"(r[1]), "=r"(r[2]), "=r"(r[3]) : "r"(addr));
}
__device__ __forceinline__ void ldsm_x4_t(uint32_t* r, uint32_t addr) {
    asm volatile("ldmatrix.sync.aligned.m8n8.x4.trans.shared.b16 {%0,%1,%2,%3}, [%4];"
                 : "=r"(r[0]), "=r"(r[1]), "=r"(r[2]), "=r"(r[3]) : "r"(addr));
}
__device__ __forceinline__ void mma16816(float* c, const uint32_t* a, const uint32_t* b) {
    asm volatile(
        "mma.sync.aligned.m16n8k16.row.col.f32.bf16.bf16.f32 "
        "{%0,%1,%2,%3}, {%4,%5,%6,%7}, {%8,%9}, {%0,%1,%2,%3};"
        : "+f"(c[0]), "+f"(c[1]), "+f"(c[2]), "+f"(c[3])
        : "r"(a[0]), "r"(a[1]), "r"(a[2]), "r"(a[3]), "r"(b[0]), "r"(b[1]));
}
__device__ __forceinline__ void cp16(uint32_t dst, const void* src) {
    asm volatile("cp.async.ca.shared.global [%0], [%1], 16;"
                 :: "r"(dst), "l"(src) : "memory");
}
__device__ __forceinline__ void cp_commit() {
    asm volatile("cp.async.commit_group;" ::: "memory");
}
template <int N>
__device__ __forceinline__ void cp_wait() {
    asm volatile("cp.async.wait_group %0;" :: "n"(N) : "memory");
}
__device__ __forceinline__ uint32_t packbf(float a, float b) {
    __nv_bfloat162 h;
    h.x = __float2bfloat16(a);
    h.y = __float2bfloat16(b);
    return *(uint32_t*)&h;
}

// ======================= fp32 -> (hi, lo) bf16 split (fused) ================
__device__ __forceinline__ void split_one(const float* __restrict__ in,
                                          __nv_bfloat16* __restrict__ hi,
                                          __nv_bfloat16* __restrict__ lo, int i) {
    float4 v = ((const float4*)in)[i];
    __nv_bfloat16 h0 = __float2bfloat16(v.x);
    __nv_bfloat16 h1 = __float2bfloat16(v.y);
    __nv_bfloat16 h2 = __float2bfloat16(v.z);
    __nv_bfloat16 h3 = __float2bfloat16(v.w);
    __nv_bfloat162 H0, H1, L0, L1;
    H0.x = h0; H0.y = h1; H1.x = h2; H1.y = h3;
    L0.x = __float2bfloat16(v.x - __bfloat162float(h0));
    L0.y = __float2bfloat16(v.y - __bfloat162float(h1));
    L1.x = __float2bfloat16(v.z - __bfloat162float(h2));
    L1.y = __float2bfloat16(v.w - __bfloat162float(h3));
    ((__nv_bfloat162*)hi)[2 * i]     = H0;
    ((__nv_bfloat162*)hi)[2 * i + 1] = H1;
    ((__nv_bfloat162*)lo)[2 * i]     = L0;
    ((__nv_bfloat162*)lo)[2 * i + 1] = L1;
}

#define NX4 (TS * DIM / 4)
#define NW4 (DIM * DIM / 4)

__global__ __launch_bounds__(256)
void split_all(const float* __restrict__ x,
               const float* __restrict__ qw, const float* __restrict__ kw,
               const float* __restrict__ vw, const float* __restrict__ ow,
               __nv_bfloat16* __restrict__ xh, __nv_bfloat16* __restrict__ xl,
               __nv_bfloat16* __restrict__ wh, __nv_bfloat16* __restrict__ wl) {
    int i = blockIdx.x * 256 + threadIdx.x;
    int z = blockIdx.y;
    if (z == 0) {
        if (i < NX4) split_one(x, xh, xl, i);
    } else {
        if (i < NW4) {
            const float* in = (z == 1) ? qw : (z == 2) ? kw : (z == 3) ? vw : ow;
            split_one(in, wh + (size_t)(z - 1) * DIM * DIM,
                          wl + (size_t)(z - 1) * DIM * DIM, i);
        }
    }
}

// ======================= mma.sync split-bf16 GEMM core ======================
// 512 threads, 16 warps (4M x 4N, 32x32 per warp), 3-stage cp.async ring.
#define SSTR 40
#define TILE_E (128 * SSTR)
#define TILE_B (TILE_E * 2)
#define BUF_E  (4 * TILE_E)
#define GNST 3
#define GEMM_SMEM_BYTES (GNST * BUF_E * 2)

struct GemmOut {
    float acc[2][4][4];
};

__device__ __forceinline__ void gemm_core(
    const __nv_bfloat16* __restrict__ Ah, const __nv_bfloat16* __restrict__ Al,
    const __nv_bfloat16* __restrict__ Wh, const __nv_bfloat16* __restrict__ Wl,
    int m0, int n0, int K, __nv_bfloat16* sm, GemmOut& out) {
    const int tid  = threadIdx.x;
    const int warp = tid >> 5, lane = tid & 31;
    const int wm   = warp & 3;       // 4 M blocks of 32
    const int wn   = warp >> 2;      // 4 N blocks of 32
    const uint32_t sbase = s2u(sm);

#pragma unroll
    for (int i = 0; i < 2; i++)
#pragma unroll
        for (int j = 0; j < 4; j++)
#pragma unroll
            for (int k = 0; k < 4; k++) out.acc[i][j][k] = 0.f;

    const __nv_bfloat16* srcs[4] = {Ah, Al, Wh, Wl};

    auto issue_chunk = [&](int c, int s) {
#pragma unroll
        for (int j = 0; j < 4; j++) {
            int i = tid + j * 512;
            int arr = i >> 9;
            int idx = i & 511;
            int row = idx >> 2, seg = idx & 3;
            const __nv_bfloat16* src = srcs[arr] +
                (size_t)((arr < 2 ? m0 : n0) + row) * K + c * 32 + seg * 8;
            uint32_t dst = sbase + (uint32_t)(s * BUF_E + arr * TILE_E + row * SSTR + seg * 8) * 2;
            cp16(dst, src);
        }
        cp_commit();
    };

    const int NC = K / 32;
    issue_chunk(0, 0);
    issue_chunk(1, 1);

    const uint32_t arow = (uint32_t)(wm * 32 + (lane & 15));
    const uint32_t acol = (uint32_t)((lane >> 4) * 16);
    const uint32_t bro  = (uint32_t)((lane & 7) + 8 * ((lane >> 4) & 1));
    const uint32_t bco  = (uint32_t)(((lane >> 3) & 1) * 16);

    int s = 0;  // stage of chunk c
    for (int c = 0; c < NC; c++) {
        if (c + 1 < NC) cp_wait<1>(); else cp_wait<0>();
        __syncthreads();
        if (c + 2 < NC) {
            int s2 = s + 2; if (s2 >= GNST) s2 -= GNST;
            issue_chunk(c + 2, s2);
        }
        const uint32_t bb = sbase + (uint32_t)(s * BUF_E) * 2;
#pragma unroll
        for (int ks = 0; ks < 2; ks++) {
            uint32_t aH[2][4], aL[2][4], bH[8], bL[8];
            const uint32_t aoff = arow * (SSTR * 2) + ks * 32 + acol;
#pragma unroll
            for (int mt = 0; mt < 2; mt++)
                ldsm_x4(aH[mt], bb + 0 * TILE_B + aoff + mt * 16 * (SSTR * 2));
#pragma unroll
            for (int p = 0; p < 2; p++) {
                uint32_t boff = (uint32_t)(wn * 32 + p * 16 + bro) * (SSTR * 2) + ks * 32 + bco;
                ldsm_x4(&bH[4 * p], bb + 2 * TILE_B + boff);
            }
#pragma unroll
            for (int mt = 0; mt < 2; mt++)
#pragma unroll
                for (int nt = 0; nt < 4; nt++)
                    mma16816(out.acc[mt][nt], aH[mt], &bH[2 * nt]);
#pragma unroll
            for (int mt = 0; mt < 2; mt++)
                ldsm_x4(aL[mt], bb + 1 * TILE_B + aoff + mt * 16 * (SSTR * 2));
#pragma unroll
            for (int mt = 0; mt < 2; mt++)
#pragma unroll
                for (int nt = 0; nt < 4; nt++)
                    mma16816(out.acc[mt][nt], aL[mt], &bH[2 * nt]);
#pragma unroll
            for (int p = 0; p < 2; p++) {
                uint32_t boff = (uint32_t)(wn * 32 + p * 16 + bro) * (SSTR * 2) + ks * 32 + bco;
                ldsm_x4(&bL[4 * p], bb + 3 * TILE_B + boff);
            }
#pragma unroll
            for (int mt = 0; mt < 2; mt++)
#pragma unroll
                for (int nt = 0; nt < 4; nt++)
                    mma16816(out.acc[mt][nt], aH[mt], &bL[2 * nt]);
        }
        if (++s == GNST) s = 0;
    }
}

// ---- fused QKV projection: z = 0 (Q, f32) / 1 (K, f32) / 2 (V, bf16 hi/lo) ----
__global__ __launch_bounds__(512)
void gemm_qkv(const __nv_bfloat16* __restrict__ xh, const __nv_bfloat16* __restrict__ xl,
              const __nv_bfloat16* __restrict__ whb, const __nv_bfloat16* __restrict__ wlb,
              const float* __restrict__ qb, const float* __restrict__ kb,
              const float* __restrict__ vb,
              float* __restrict__ gq, float* __restrict__ gk,
              __nv_bfloat16* __restrict__ vh, __nv_bfloat16* __restrict__ vl) {
    extern __shared__ __nv_bfloat16 sm[];
    const int z  = blockIdx.z;
    const int m0 = blockIdx.y * 128, n0 = blockIdx.x * 128;
    const size_t WSZ = (size_t)DIM * DIM;
    const __nv_bfloat16* Wh = whb + (size_t)z * WSZ;
    const __nv_bfloat16* Wl = wlb + (size_t)z * WSZ;
    const float* bias = (z == 0) ? qb : (z == 1) ? kb : vb;

    GemmOut out;
    gemm_core(xh, xl, Wh, Wl, m0, n0, DIM, sm, out);

    const int warp = threadIdx.x >> 5, lane = threadIdx.x & 31;
    const int row_base = m0 + (warp & 3) * 32 + (lane >> 2);
    const int col_base = n0 + (warp >> 2) * 32 + (lane & 3) * 2;
    float* Cf = (z == 0) ? gq : gk;
#pragma unroll
    for (int mt = 0; mt < 2; mt++) {
#pragma unroll
        for (int nt = 0; nt < 4; nt++) {
            int r = row_base + mt * 16;
            int cc = col_base + nt * 8;
            float bx = bias[cc], by = bias[cc + 1];
            float v00 = out.acc[mt][nt][0] + bx, v01 = out.acc[mt][nt][1] + by;
            float v10 = out.acc[mt][nt][2] + bx, v11 = out.acc[mt][nt][3] + by;
            if (z < 2) {
                *(float2*)(Cf + (size_t)r * DIM + cc)       = make_float2(v00, v01);
                *(float2*)(Cf + (size_t)(r + 8) * DIM + cc) = make_float2(v10, v11);
            } else {
                uint32_t h0 = packbf(v00, v01);
                uint32_t h1 = packbf(v10, v11);
                __nv_bfloat162 H0 = *(__nv_bfloat162*)&h0;
                __nv_bfloat162 H1 = *(__nv_bfloat162*)&h1;
                uint32_t l0 = packbf(v00 - __bfloat162float(H0.x), v01 - __bfloat162float(H0.y));
                uint32_t l1 = packbf(v10 - __bfloat162float(H1.x), v11 - __bfloat162float(H1.y));
                *(uint32_t*)(vh + (size_t)r * DIM + cc)       = h0;
                *(uint32_t*)(vh + (size_t)(r + 8) * DIM + cc) = h1;
                *(uint32_t*)(vl + (size_t)r * DIM + cc)       = l0;
                *(uint32_t*)(vl + (size_t)(r + 8) * DIM + cc) = l1;
            }
        }
    }
}

// ---- O projection (f32 out) ----
__global__ __launch_bounds__(512)
void gemm_o(const __nv_bfloat16* __restrict__ Ah, const __nv_bfloat16* __restrict__ Al,
            const __nv_bfloat16* __restrict__ Wh, const __nv_bfloat16* __restrict__ Wl,
            const float* __restrict__ bias, float* __restrict__ Cf) {
    extern __shared__ __nv_bfloat16 sm[];
    const int m0 = blockIdx.y * 128, n0 = blockIdx.x * 128;
    GemmOut out;
    gemm_core(Ah, Al, Wh, Wl, m0, n0, DIM, sm, out);

    const int warp = threadIdx.x >> 5, lane = threadIdx.x & 31;
    const int row_base = m0 + (warp & 3) * 32 + (lane >> 2);
    const int col_base = n0 + (warp >> 2) * 32 + (lane & 3) * 2;
#pragma unroll
    for (int mt = 0; mt < 2; mt++) {
#pragma unroll
        for (int nt = 0; nt < 4; nt++) {
            int r = row_base + mt * 16;
            int cc = col_base + nt * 8;
            float bx = bias[cc], by = bias[cc + 1];
            *(float2*)(Cf + (size_t)r * DIM + cc) =
                make_float2(out.acc[mt][nt][0] + bx, out.acc[mt][nt][1] + by);
            *(float2*)(Cf + (size_t)(r + 8) * DIM + cc) =
                make_float2(out.acc[mt][nt][2] + bx, out.acc[mt][nt][3] + by);
        }
    }
}

// ======================= RMSNorm + RoPE -> bf16 hi/lo =======================
__global__ __launch_bounds__(256)
void norm_rope_kernel(const float* __restrict__ q, const float* __restrict__ k,
                      const float* __restrict__ freqs,
                      const float* __restrict__ nqw, const float* __restrict__ nkw,
                      __nv_bfloat16* __restrict__ QH, __nv_bfloat16* __restrict__ QL,
                      __nv_bfloat16* __restrict__ KH, __nv_bfloat16* __restrict__ KL) {
    const int row = blockIdx.x;
    const float* x = (blockIdx.y == 0 ? q : k) + (size_t)row * DIM;
    const float* w = (blockIdx.y == 0) ? nqw : nkw;
    __nv_bfloat16* OH = (blockIdx.y == 0) ? QH : KH;
    __nv_bfloat16* OL = (blockIdx.y == 0) ? QL : KL;
    const float sc = (blockIdx.y == 0) ? SCALE : 1.f;
    const int tid = threadIdx.x;

    float ss = 0.f;
    for (int i = tid; i < DIM; i += 256) { float v = x[i]; ss += v * v; }
#pragma unroll
    for (int o = 16; o > 0; o >>= 1) ss += __shfl_xor_sync(~0u, ss, o);
    __shared__ float warpsum[8];
    if ((tid & 31) == 0) warpsum[tid >> 5] = ss;
    __syncthreads();
    float tot = 0.f;
#pragma unroll
    for (int i = 0; i < 8; i++) tot += warpsum[i];
    const float rs = rsqrtf(tot / (float)DIM + EPS);

    const int tv = row % VS;
    const int f  = tv / TPF;
    const int r  = tv % TPF;
    const int hh = r / NW;
    const int ww = r % NW;

    for (int p = tid; p < DIM / 2; p += 256) {
        int c = p & 63;
        int idx = (c < 22) ? f : ((c < 43) ? hh : ww);
        float ang = freqs[idx * 64 + c];
        float sn, cs;
        sincosf(ang, &sn, &cs);
        float x0 = x[2 * p]     * rs * w[2 * p];
        float x1 = x[2 * p + 1] * rs * w[2 * p + 1];
        float r0 = (x0 * cs - x1 * sn) * sc;
        float r1 = (x0 * sn + x1 * cs) * sc;
        uint32_t h = packbf(r0, r1);
        __nv_bfloat162 H = *(__nv_bfloat162*)&h;
        uint32_t l = packbf(r0 - __bfloat162float(H.x), r1 - __bfloat162float(H.y));
        *(uint32_t*)(OH + (size_t)row * DIM + 2 * p) = h;
        *(uint32_t*)(OL + (size_t)row * DIM + 2 * p) = l;
    }
}

// ======================= mma.sync flash attention =======================
#define AQB  128
#define ASTR 136
#define AQR  (AQB * ASTR)
#define ATL  (32 * ASTR)
#define ASTAGE (4 * ATL)
#define ANST 4
#define ATT_SMEM_BYTES ((2 * AQR + 3 * ASTAGE) * 2)   // stage 3 lives in Q region

__global__ __launch_bounds__(256)
void attn_mma(const __nv_bfloat16* __restrict__ Qh, const __nv_bfloat16* __restrict__ Ql,
              const __nv_bfloat16* __restrict__ Kh, const __nv_bfloat16* __restrict__ Kl,
              const __nv_bfloat16* __restrict__ Vh, const __nv_bfloat16* __restrict__ Vl,
              __nv_bfloat16* __restrict__ Oh, __nv_bfloat16* __restrict__ Ol) {
    extern __shared__ __nv_bfloat16 smb[];
    const uint32_t sbase = s2u(smb);
    const int head = blockIdx.y;
    const int q0   = blockIdx.x * AQB;
    const int v    = q0 / VS;
    const int col0 = head * HD;
    const int tid  = threadIdx.x;
    const int warp = tid >> 5, lane = tid & 31;

    const int f_lo = (q0 % VS) / TPF;
    const int f_hi = ((q0 + AQB - 1) % VS) / TPF;
    const int span = (f_hi != f_lo);
    const int fw   = ((q0 + warp * 16) % VS) / TPF;

    for (int i = tid; i < AQB * 16; i += 256) {
        int r = i >> 4, seg = i & 15;
        *(uint4*)&smb[r * ASTR + seg * 8] =
            *(const uint4*)&Qh[(size_t)(q0 + r) * DIM + col0 + seg * 8];
        *(uint4*)&smb[AQR + r * ASTR + seg * 8] =
            *(const uint4*)&Ql[(size_t)(q0 + r) * DIM + col0 + seg * 8];
    }

    const int baseA = v * VS;
    const int baseBv = (1 - v) * VS;
    const int NT = 56 + (span ? 28 : 14);

    const __nv_bfloat16* ptrs[4] = {Kh, Kl, Vh, Vl};

    auto tile_base = [&](int t) -> int {
        if (t < 56) return baseA + t * 32;
        int tt = t - 56;
        int fi = (tt < 14) ? f_lo : f_hi;
        int ttt = (tt < 14) ? tt : tt - 14;
        return baseBv + fi * TPF + ttt * 32;
    };

    auto stage_off = [&](int s) -> uint32_t {
        return (s == 3) ? 0u : (uint32_t)(2 * AQR + s * ASTAGE);
    };

    auto issue_tile = [&](int t, int s) {
        int kb = tile_base(t);
        uint32_t so = stage_off(s);
#pragma unroll
        for (int j = 0; j < 8; j++) {
            int i = tid + j * 256;
            int arr = i >> 9;
            int idx = i & 511;
            int r = idx >> 4, seg = idx & 15;
            const __nv_bfloat16* src = ptrs[arr] + (size_t)(kb + r) * DIM + col0 + seg * 8;
            uint32_t dst = sbase + (uint32_t)(so + arr * ATL + r * ASTR + seg * 8) * 2;
            cp16(dst, src);
        }
        cp_commit();
    };

    issue_tile(0, 0);
    issue_tile(1, 1);
    __syncthreads();

    const uint32_t q_aoff = (uint32_t)(warp * 16 + (lane & 15)) * (ASTR * 2)
                          + (uint32_t)((lane >> 4) * 16);
    uint32_t aQh[8][4], aQl[8][4];
#pragma unroll
    for (int ks = 0; ks < 8; ks++) {
        ldsm_x4(aQh[ks], sbase + q_aoff + ks * 32);
        ldsm_x4(aQl[ks], sbase + AQR * 2 + q_aoff + ks * 32);
    }

    float m[2] = {-1e30f, -1e30f};
    float l[2] = {0.f, 0.f};
    float acc[16][4];
#pragma unroll
    for (int nt = 0; nt < 16; nt++)
#pragma unroll
        for (int j = 0; j < 4; j++) acc[nt][j] = 0.f;

    const uint32_t k_bro  = (uint32_t)((lane & 7) + 8 * ((lane >> 4) & 1));
    const uint32_t k_bco  = (uint32_t)(((lane >> 3) & 1) * 16);
    const uint32_t v_row  = (uint32_t)(lane & 15);
    const uint32_t v_cofs = (uint32_t)(8 * ((lane >> 4) & 1));

    int s = 0;
    for (int t = 0; t < NT; t++) {
        if (t + 1 < NT) cp_wait<1>(); else cp_wait<0>();
        __syncthreads();
        if (t + 2 < NT) {
            int s2 = s + 2; if (s2 >= ANST) s2 -= ANST;
            issue_tile(t + 2, s2);
        }

        bool act = (t < 56) || (((t - 56) < 14 ? f_lo : f_hi) == fw);

        if (act) {
            const uint32_t st = sbase + stage_off(s) * 2;
            const uint32_t khb = st, klb = st + ATL * 2, vhb = st + 2 * ATL * 2, vlb = st + 3 * ATL * 2;

            float S[4][4];
#pragma unroll
            for (int nt = 0; nt < 4; nt++)
#pragma unroll
                for (int j = 0; j < 4; j++) S[nt][j] = 0.f;

#pragma unroll
            for (int ks = 0; ks < 8; ks++) {
                uint32_t bKh[8], bKl[8];
#pragma unroll
                for (int p = 0; p < 2; p++) {
                    uint32_t boff = (uint32_t)(p * 16 + k_bro) * (ASTR * 2) + ks * 32 + k_bco;
                    ldsm_x4(&bKh[4 * p], khb + boff);
                    ldsm_x4(&bKl[4 * p], klb + boff);
                }
#pragma unroll
                for (int nt = 0; nt < 4; nt++) {
                    mma16816(S[nt], aQh[ks], &bKh[2 * nt]);
                    mma16816(S[nt], aQh[ks], &bKl[2 * nt]);
                    mma16816(S[nt], aQl[ks], &bKh[2 * nt]);
                }
            }

            float mn[2], corr[2];
#pragma unroll
            for (int j = 0; j < 2; j++) {
                float mx = -1e30f;
#pragma unroll
                for (int nt = 0; nt < 4; nt++)
                    mx = fmaxf(mx, fmaxf(S[nt][2 * j], S[nt][2 * j + 1]));
                mx = fmaxf(mx, __shfl_xor_sync(~0u, mx, 1));
                mx = fmaxf(mx, __shfl_xor_sync(~0u, mx, 2));
                mn[j] = fmaxf(m[j], mx);
                corr[j] = __expf(m[j] - mn[j]);
            }
            bool resc = !__all_sync(~0u, (mn[0] == m[0]) && (mn[1] == m[1]));
            m[0] = mn[0]; m[1] = mn[1];

            uint32_t ph[4][2], pl[4][2];
#pragma unroll
            for (int j = 0; j < 2; j++) {
                float rs = 0.f;
#pragma unroll
                for (int nt = 0; nt < 4; nt++) {
                    float e0 = __expf(S[nt][2 * j]     - mn[j]);
                    float e1 = __expf(S[nt][2 * j + 1] - mn[j]);
                    S[nt][2 * j] = e0; S[nt][2 * j + 1] = e1;
                    rs += e0 + e1;
                }
                rs += __shfl_xor_sync(~0u, rs, 1);
                rs += __shfl_xor_sync(~0u, rs, 2);
                l[j] = l[j] * corr[j] + rs;
            }
            if (resc) {
#pragma unroll
                for (int nt = 0; nt < 16; nt++) {
                    acc[nt][0] *= corr[0]; acc[nt][1] *= corr[0];
                    acc[nt][2] *= corr[1]; acc[nt][3] *= corr[1];
                }
            }
#pragma unroll
            for (int nt = 0; nt < 4; nt++) {
#pragma unroll
                for (int j = 0; j < 2; j++) {
                    float e0 = S[nt][2 * j], e1 = S[nt][2 * j + 1];
                    uint32_t h = packbf(e0, e1);
                    __nv_bfloat162 H = *(__nv_bfloat162*)&h;
                    ph[nt][j] = h;
                    pl[nt][j] = packbf(e0 - __bfloat162float(H.x), e1 - __bfloat162float(H.y));
                }
            }

#pragma unroll
            for (int ks2 = 0; ks2 < 2; ks2++) {
                uint32_t aPh[4] = {ph[2 * ks2][0], ph[2 * ks2][1], ph[2 * ks2 + 1][0], ph[2 * ks2 + 1][1]};
                uint32_t aPl[4] = {pl[2 * ks2][0], pl[2 * ks2][1], pl[2 * ks2 + 1][0], pl[2 * ks2 + 1][1]};
#pragma unroll
                for (int dp = 0; dp < 8; dp++) {
                    uint32_t bVh[4], bVl[4];
                    uint32_t voff = (uint32_t)(ks2 * 16 + v_row) * (ASTR * 2)
                                  + (uint32_t)(dp * 16 + v_cofs) * 2;
                    ldsm_x4_t(bVh, vhb + voff);
                    mma16816(acc[2 * dp],     aPh, &bVh[0]);
                    mma16816(acc[2 * dp + 1], aPh, &bVh[2]);
                    mma16816(acc[2 * dp],     aPl, &bVh[0]);
                    mma16816(acc[2 * dp + 1], aPl, &bVh[2]);
                    ldsm_x4_t(bVl, vlb + voff);
                    mma16816(acc[2 * dp],     aPh, &bVl[0]);
                    mma16816(acc[2 * dp + 1], aPh, &bVl[2]);
                }
            }
        }
        if (++s == ANST) s = 0;
    }

#pragma unroll
    for (int j = 0; j < 2; j++) {
        float inv = 1.f / l[j];
        int row = q0 + warp * 16 + (lane >> 2) + 8 * j;
#pragma unroll
        for (int nt = 0; nt < 16; nt++) {
            float o0 = acc[nt][2 * j] * inv;
            float o1 = acc[nt][2 * j + 1] * inv;
            uint32_t h = packbf(o0, o1);
            __nv_bfloat162 H = *(__nv_bfloat162*)&h;
            uint32_t lo = packbf(o0 - __bfloat162float(H.x), o1 - __bfloat162float(H.y));
            size_t off = (size_t)row * DIM + col0 + nt * 8 + 2 * (lane & 3);
            *(uint32_t*)(Oh + off) = h;
            *(uint32_t*)(Ol + off) = lo;
        }
    }
}

// ======================= launch =======================
extern "C" void kernel_launch(void* const* d_in, const int* in_sizes, int n_in,
                              void* d_out, int out_size) {
    const float* x     = (const float*)d_in[0];
    const float* freqs = (const float*)d_in[1];
    const float* q_w   = (const float*)d_in[2];
    const float* q_b   = (const float*)d_in[3];
    const float* k_w   = (const float*)d_in[4];
    const float* k_b   = (const float*)d_in[5];
    const float* v_w   = (const float*)d_in[6];
    const float* v_b   = (const float*)d_in[7];
    const float* o_w   = (const float*)d_in[8];
    const float* o_b   = (const float*)d_in[9];
    const float* nqw   = (const float*)d_in[10];
    const float* nkw   = (const float*)d_in[11];

    float *gq, *gk;
    __nv_bfloat16 *xh, *xl, *qh, *ql, *kh, *kl, *vh, *vl, *oh, *ol, *wh, *wl;
    cudaGetSymbolAddress((void**)&gq, g_q);
    cudaGetSymbolAddress((void**)&gk, g_k);
    cudaGetSymbolAddress((void**)&xh, g_xh);
    cudaGetSymbolAddress((void**)&xl, g_xl);
    cudaGetSymbolAddress((void**)&qh, g_qh);
    cudaGetSymbolAddress((void**)&ql, g_ql);
    cudaGetSymbolAddress((void**)&kh, g_kh);
    cudaGetSymbolAddress((void**)&kl, g_kl);
    cudaGetSymbolAddress((void**)&vh, g_vh);
    cudaGetSymbolAddress((void**)&vl, g_vl);
    cudaGetSymbolAddress((void**)&oh, g_oh);
    cudaGetSymbolAddress((void**)&ol, g_ol);
    cudaGetSymbolAddress((void**)&wh, g_wh);
    cudaGetSymbolAddress((void**)&wl, g_wl);

    const size_t WSZ = (size_t)DIM * DIM;
    __nv_bfloat16 *owh = wh + 3 * WSZ, *owl = wl + 3 * WSZ;

    // one fused split launch (x + 4 weights)
    split_all<<<dim3((NX4 + 255) / 256, 5), 256>>>(x, q_w, k_w, v_w, o_w, xh, xl, wh, wl);

    cudaFuncSetAttribute(gemm_qkv, cudaFuncAttributeMaxDynamicSharedMemorySize,
                         GEMM_SMEM_BYTES);
    cudaFuncSetAttribute(gemm_o, cudaFuncAttributeMaxDynamicSharedMemorySize,
                         GEMM_SMEM_BYTES);
    gemm_qkv<<<dim3(DIM / 128, TS / 128, 3), 512, GEMM_SMEM_BYTES>>>(
        xh, xl, wh, wl, q_b, k_b, v_b, gq, gk, vh, vl);

    norm_rope_kernel<<<dim3(TS, 2), 256>>>(gq, gk, freqs, nqw, nkw, qh, ql, kh, kl);

    cudaFuncSetAttribute(attn_mma, cudaFuncAttributeMaxDynamicSharedMemorySize,
                         ATT_SMEM_BYTES);
    attn_mma<<<dim3(TS / AQB, NH), 256, ATT_SMEM_BYTES>>>(qh, ql, kh, kl, vh, vl, oh, ol);

    gemm_o<<<dim3(DIM / 128, TS / 128), 512, GEMM_SMEM_BYTES>>>(
        oh, ol, owh, owl, o_b, (float*)d_out);
}

// round 10
// speedup vs baseline: 1.0926x; 1.0926x over previous
#include <cuda_runtime.h>
#include <cuda_bf16.h>
#include <cstdint>

#define TS   3584
#define DIM  1536
#define NH   12
#define HD   128
#define VS   1792
#define TPF  448
#define NW   28
#define EPS  1e-6f
#define SCALE 0.08838834764831845f   // 1/sqrt(128)

// -------- scratch (device globals; no allocations allowed) --------
__device__ float g_q[(size_t)TS * DIM];
__device__ float g_k[(size_t)TS * DIM];
__device__ __nv_bfloat16 g_xh[(size_t)TS * DIM];
__device__ __nv_bfloat16 g_xl[(size_t)TS * DIM];
__device__ __nv_bfloat16 g_qh[(size_t)TS * DIM];
__device__ __nv_bfloat16 g_ql[(size_t)TS * DIM];
__device__ __nv_bfloat16 g_kh[(size_t)TS * DIM];
__device__ __nv_bfloat16 g_kl[(size_t)TS * DIM];
__device__ __nv_bfloat16 g_vh[(size_t)TS * DIM];
__device__ __nv_bfloat16 g_vl[(size_t)TS * DIM];
__device__ __nv_bfloat16 g_oh[(size_t)TS * DIM];
__device__ __nv_bfloat16 g_ol[(size_t)TS * DIM];
__device__ __nv_bfloat16 g_wh[4][(size_t)DIM * DIM];
__device__ __nv_bfloat16 g_wl[4][(size_t)DIM * DIM];

// ======================= PTX helpers =======================
__device__ __forceinline__ uint32_t s2u(const void* p) {
    uint32_t a;
    asm("{ .reg .u64 t; cvta.to.shared.u64 t, %1; cvt.u32.u64 %0, t; }"
        : "=r"(a) : "l"(p));
    return a;
}
__device__ __forceinline__ void ldsm_x4(uint32_t* r, uint32_t addr) {
    asm volatile("ldmatrix.sync.aligned.m8n8.x4.shared.b16 {%0,%1,%2,%3}, [%4];"
                 : "=r"(r[0]), "=r"(r[1]), "=r"(r[2]), "=r"(r[3]) : "r"(addr));
}
__device__ __forceinline__ void ldsm_x4_t(uint32_t* r, uint32_t addr) {
    asm volatile("ldmatrix.sync.aligned.m8n8.x4.trans.shared.b16 {%0,%1,%2,%3}, [%4];"
                 : "=r"(r[0]), "=r"(r[1]), "=r"(r[2]), "=r"(r[3]) : "r"(addr));
}
__device__ __forceinline__ void mma16816(float* c, const uint32_t* a, const uint32_t* b) {
    asm volatile(
        "mma.sync.aligned.m16n8k16.row.col.f32.bf16.bf16.f32 "
        "{%0,%1,%2,%3}, {%4,%5,%6,%7}, {%8,%9}, {%0,%1,%2,%3};"
        : "+f"(c[0]), "+f"(c[1]), "+f"(c[2]), "+f"(c[3])
        : "r"(a[0]), "r"(a[1]), "r"(a[2]), "r"(a[3]), "r"(b[0]), "r"(b[1]));
}
__device__ __forceinline__ void cp16(uint32_t dst, const void* src) {
    asm volatile("cp.async.ca.shared.global [%0], [%1], 16;"
                 :: "r"(dst), "l"(src) : "memory");
}
__device__ __forceinline__ void cp_commit() {
    asm volatile("cp.async.commit_group;" ::: "memory");
}
template <int N>
__device__ __forceinline__ void cp_wait() {
    asm volatile("cp.async.wait_group %0;" :: "n"(N) : "memory");
}
__device__ __forceinline__ uint32_t packbf(float a, float b) {
    __nv_bfloat162 h;
    h.x = __float2bfloat16(a);
    h.y = __float2bfloat16(b);
    return *(uint32_t*)&h;
}

// ======================= fp32 -> (hi, lo) bf16 split (fused) ================
__device__ __forceinline__ void split_one(const float* __restrict__ in,
                                          __nv_bfloat16* __restrict__ hi,
                                          __nv_bfloat16* __restrict__ lo, int i) {
    float4 v = ((const float4*)in)[i];
    __nv_bfloat16 h0 = __float2bfloat16(v.x);
    __nv_bfloat16 h1 = __float2bfloat16(v.y);
    __nv_bfloat16 h2 = __float2bfloat16(v.z);
    __nv_bfloat16 h3 = __float2bfloat16(v.w);
    __nv_bfloat162 H0, H1, L0, L1;
    H0.x = h0; H0.y = h1; H1.x = h2; H1.y = h3;
    L0.x = __float2bfloat16(v.x - __bfloat162float(h0));
    L0.y = __float2bfloat16(v.y - __bfloat162float(h1));
    L1.x = __float2bfloat16(v.z - __bfloat162float(h2));
    L1.y = __float2bfloat16(v.w - __bfloat162float(h3));
    ((__nv_bfloat162*)hi)[2 * i]     = H0;
    ((__nv_bfloat162*)hi)[2 * i + 1] = H1;
    ((__nv_bfloat162*)lo)[2 * i]     = L0;
    ((__nv_bfloat162*)lo)[2 * i + 1] = L1;
}

#define NX4 (TS * DIM / 4)
#define NW4 (DIM * DIM / 4)

__global__ __launch_bounds__(256)
void split_all(const float* __restrict__ x,
               const float* __restrict__ qw, const float* __restrict__ kw,
               const float* __restrict__ vw, const float* __restrict__ ow,
               __nv_bfloat16* __restrict__ xh, __nv_bfloat16* __restrict__ xl,
               __nv_bfloat16* __restrict__ wh, __nv_bfloat16* __restrict__ wl) {
    int i = blockIdx.x * 256 + threadIdx.x;
    int z = blockIdx.y;
    if (z == 0) {
        if (i < NX4) split_one(x, xh, xl, i);
    } else {
        if (i < NW4) {
            const float* in = (z == 1) ? qw : (z == 2) ? kw : (z == 3) ? vw : ow;
            split_one(in, wh + (size_t)(z - 1) * DIM * DIM,
                          wl + (size_t)(z - 1) * DIM * DIM, i);
        }
    }
}

// ======================= mma.sync split-bf16 GEMM core ======================
// 256 threads, 8 warps (2M x 4N, 64x32 per warp), 2-stage cp.async ring.
// SSTR=40 (80B rows: 16B-aligned, ldsm conflict-free). 80KB smem -> 2 CTAs/SM.
#define SSTR 40
#define TILE_E (128 * SSTR)
#define TILE_B (TILE_E * 2)
#define BUF_E  (4 * TILE_E)
#define GNST 2
#define GEMM_SMEM_BYTES (GNST * BUF_E * 2)   // 81920

struct GemmOut {
    float acc[4][4][4];
};

__device__ __forceinline__ void gemm_core(
    const __nv_bfloat16* __restrict__ Ah, const __nv_bfloat16* __restrict__ Al,
    const __nv_bfloat16* __restrict__ Wh, const __nv_bfloat16* __restrict__ Wl,
    int m0, int n0, int K, __nv_bfloat16* sm, GemmOut& out) {
    const int tid  = threadIdx.x;
    const int warp = tid >> 5, lane = tid & 31;
    const int wm   = warp & 1;
    const int wn   = warp >> 1;
    const uint32_t sbase = s2u(sm);

#pragma unroll
    for (int i = 0; i < 4; i++)
#pragma unroll
        for (int j = 0; j < 4; j++)
#pragma unroll
            for (int k = 0; k < 4; k++) out.acc[i][j][k] = 0.f;

    const __nv_bfloat16* srcs[4] = {Ah, Al, Wh, Wl};

    auto issue_chunk = [&](int c, int s) {
#pragma unroll
        for (int j = 0; j < 8; j++) {
            int i = tid + j * 256;
            int arr = i >> 9;
            int idx = i & 511;
            int row = idx >> 2, seg = idx & 3;
            const __nv_bfloat16* src = srcs[arr] +
                (size_t)((arr < 2 ? m0 : n0) + row) * K + c * 32 + seg * 8;
            uint32_t dst = sbase + (uint32_t)(s * BUF_E + arr * TILE_E + row * SSTR + seg * 8) * 2;
            cp16(dst, src);
        }
        cp_commit();
    };

    const int NC = K / 32;
    issue_chunk(0, 0);

    const uint32_t arow = (uint32_t)(wm * 64 + (lane & 15));
    const uint32_t acol = (uint32_t)((lane >> 4) * 16);
    const uint32_t bro  = (uint32_t)((lane & 7) + 8 * ((lane >> 4) & 1));
    const uint32_t bco  = (uint32_t)(((lane >> 3) & 1) * 16);

    for (int c = 0; c < NC; c++) {
        cp_wait<0>();            // chunk c arrived
        __syncthreads();         // all warps done with chunk c-1 (its stage is free)
        if (c + 1 < NC) issue_chunk(c + 1, (c + 1) & 1);
        const uint32_t bb = sbase + (uint32_t)((c & 1) * BUF_E) * 2;
#pragma unroll
        for (int ks = 0; ks < 2; ks++) {
            uint32_t aH[4][4], aL[4][4], bH[8], bL[8];
            const uint32_t aoff = arow * (SSTR * 2) + ks * 32 + acol;
#pragma unroll
            for (int mt = 0; mt < 4; mt++)
                ldsm_x4(aH[mt], bb + 0 * TILE_B + aoff + mt * 16 * (SSTR * 2));
#pragma unroll
            for (int p = 0; p < 2; p++) {
                uint32_t boff = (uint32_t)(wn * 32 + p * 16 + bro) * (SSTR * 2) + ks * 32 + bco;
                ldsm_x4(&bH[4 * p], bb + 2 * TILE_B + boff);
            }
#pragma unroll
            for (int mt = 0; mt < 4; mt++)
#pragma unroll
                for (int nt = 0; nt < 4; nt++)
                    mma16816(out.acc[mt][nt], aH[mt], &bH[2 * nt]);
#pragma unroll
            for (int mt = 0; mt < 4; mt++)
                ldsm_x4(aL[mt], bb + 1 * TILE_B + aoff + mt * 16 * (SSTR * 2));
#pragma unroll
            for (int mt = 0; mt < 4; mt++)
#pragma unroll
                for (int nt = 0; nt < 4; nt++)
                    mma16816(out.acc[mt][nt], aL[mt], &bH[2 * nt]);
#pragma unroll
            for (int p = 0; p < 2; p++) {
                uint32_t boff = (uint32_t)(wn * 32 + p * 16 + bro) * (SSTR * 2) + ks * 32 + bco;
                ldsm_x4(&bL[4 * p], bb + 3 * TILE_B + boff);
            }
#pragma unroll
            for (int mt = 0; mt < 4; mt++)
#pragma unroll
                for (int nt = 0; nt < 4; nt++)
                    mma16816(out.acc[mt][nt], aH[mt], &bL[2 * nt]);
        }
    }
}

// ---- fused QKV projection: z = 0 (Q, f32) / 1 (K, f32) / 2 (V, bf16 hi/lo) ----
__global__ __launch_bounds__(256, 2)
void gemm_qkv(const __nv_bfloat16* __restrict__ xh, const __nv_bfloat16* __restrict__ xl,
              const __nv_bfloat16* __restrict__ whb, const __nv_bfloat16* __restrict__ wlb,
              const float* __restrict__ qb, const float* __restrict__ kb,
              const float* __restrict__ vb,
              float* __restrict__ gq, float* __restrict__ gk,
              __nv_bfloat16* __restrict__ vh, __nv_bfloat16* __restrict__ vl) {
    extern __shared__ __nv_bfloat16 sm[];
    const int z  = blockIdx.z;
    const int m0 = blockIdx.y * 128, n0 = blockIdx.x * 128;
    const size_t WSZ = (size_t)DIM * DIM;
    const __nv_bfloat16* Wh = whb + (size_t)z * WSZ;
    const __nv_bfloat16* Wl = wlb + (size_t)z * WSZ;
    const float* bias = (z == 0) ? qb : (z == 1) ? kb : vb;

    GemmOut out;
    gemm_core(xh, xl, Wh, Wl, m0, n0, DIM, sm, out);

    const int warp = threadIdx.x >> 5, lane = threadIdx.x & 31;
    const int row_base = m0 + (warp & 1) * 64 + (lane >> 2);
    const int col_base = n0 + (warp >> 1) * 32 + (lane & 3) * 2;
    float* Cf = (z == 0) ? gq : gk;
#pragma unroll
    for (int mt = 0; mt < 4; mt++) {
#pragma unroll
        for (int nt = 0; nt < 4; nt++) {
            int r = row_base + mt * 16;
            int cc = col_base + nt * 8;
            float bx = bias[cc], by = bias[cc + 1];
            float v00 = out.acc[mt][nt][0] + bx, v01 = out.acc[mt][nt][1] + by;
            float v10 = out.acc[mt][nt][2] + bx, v11 = out.acc[mt][nt][3] + by;
            if (z < 2) {
                *(float2*)(Cf + (size_t)r * DIM + cc)       = make_float2(v00, v01);
                *(float2*)(Cf + (size_t)(r + 8) * DIM + cc) = make_float2(v10, v11);
            } else {
                uint32_t h0 = packbf(v00, v01);
                uint32_t h1 = packbf(v10, v11);
                __nv_bfloat162 H0 = *(__nv_bfloat162*)&h0;
                __nv_bfloat162 H1 = *(__nv_bfloat162*)&h1;
                uint32_t l0 = packbf(v00 - __bfloat162float(H0.x), v01 - __bfloat162float(H0.y));
                uint32_t l1 = packbf(v10 - __bfloat162float(H1.x), v11 - __bfloat162float(H1.y));
                *(uint32_t*)(vh + (size_t)r * DIM + cc)       = h0;
                *(uint32_t*)(vh + (size_t)(r + 8) * DIM + cc) = h1;
                *(uint32_t*)(vl + (size_t)r * DIM + cc)       = l0;
                *(uint32_t*)(vl + (size_t)(r + 8) * DIM + cc) = l1;
            }
        }
    }
}

// ---- O projection (f32 out) ----
__global__ __launch_bounds__(256, 2)
void gemm_o(const __nv_bfloat16* __restrict__ Ah, const __nv_bfloat16* __restrict__ Al,
            const __nv_bfloat16* __restrict__ Wh, const __nv_bfloat16* __restrict__ Wl,
            const float* __restrict__ bias, float* __restrict__ Cf) {
    extern __shared__ __nv_bfloat16 sm[];
    const int m0 = blockIdx.y * 128, n0 = blockIdx.x * 128;
    GemmOut out;
    gemm_core(Ah, Al, Wh, Wl, m0, n0, DIM, sm, out);

    const int warp = threadIdx.x >> 5, lane = threadIdx.x & 31;
    const int row_base = m0 + (warp & 1) * 64 + (lane >> 2);
    const int col_base = n0 + (warp >> 1) * 32 + (lane & 3) * 2;
#pragma unroll
    for (int mt = 0; mt < 4; mt++) {
#pragma unroll
        for (int nt = 0; nt < 4; nt++) {
            int r = row_base + mt * 16;
            int cc = col_base + nt * 8;
            float bx = bias[cc], by = bias[cc + 1];
            *(float2*)(Cf + (size_t)r * DIM + cc) =
                make_float2(out.acc[mt][nt][0] + bx, out.acc[mt][nt][1] + by);
            *(float2*)(Cf + (size_t)(r + 8) * DIM + cc) =
                make_float2(out.acc[mt][nt][2] + bx, out.acc[mt][nt][3] + by);
        }
    }
}

// ======================= RMSNorm + RoPE -> bf16 hi/lo =======================
__global__ __launch_bounds__(256)
void norm_rope_kernel(const float* __restrict__ q, const float* __restrict__ k,
                      const float* __restrict__ freqs,
                      const float* __restrict__ nqw, const float* __restrict__ nkw,
                      __nv_bfloat16* __restrict__ QH, __nv_bfloat16* __restrict__ QL,
                      __nv_bfloat16* __restrict__ KH, __nv_bfloat16* __restrict__ KL) {
    const int row = blockIdx.x;
    const float* x = (blockIdx.y == 0 ? q : k) + (size_t)row * DIM;
    const float* w = (blockIdx.y == 0) ? nqw : nkw;
    __nv_bfloat16* OH = (blockIdx.y == 0) ? QH : KH;
    __nv_bfloat16* OL = (blockIdx.y == 0) ? QL : KL;
    const float sc = (blockIdx.y == 0) ? SCALE : 1.f;
    const int tid = threadIdx.x;

    float ss = 0.f;
    for (int i = tid; i < DIM; i += 256) { float v = x[i]; ss += v * v; }
#pragma unroll
    for (int o = 16; o > 0; o >>= 1) ss += __shfl_xor_sync(~0u, ss, o);
    __shared__ float warpsum[8];
    if ((tid & 31) == 0) warpsum[tid >> 5] = ss;
    __syncthreads();
    float tot = 0.f;
#pragma unroll
    for (int i = 0; i < 8; i++) tot += warpsum[i];
    const float rs = rsqrtf(tot / (float)DIM + EPS);

    const int tv = row % VS;
    const int f  = tv / TPF;
    const int r  = tv % TPF;
    const int hh = r / NW;
    const int ww = r % NW;

    for (int p = tid; p < DIM / 2; p += 256) {
        int c = p & 63;
        int idx = (c < 22) ? f : ((c < 43) ? hh : ww);
        float ang = freqs[idx * 64 + c];
        float sn, cs;
        sincosf(ang, &sn, &cs);
        float x0 = x[2 * p]     * rs * w[2 * p];
        float x1 = x[2 * p + 1] * rs * w[2 * p + 1];
        float r0 = (x0 * cs - x1 * sn) * sc;
        float r1 = (x0 * sn + x1 * cs) * sc;
        uint32_t h = packbf(r0, r1);
        __nv_bfloat162 H = *(__nv_bfloat162*)&h;
        uint32_t l = packbf(r0 - __bfloat162float(H.x), r1 - __bfloat162float(H.y));
        *(uint32_t*)(OH + (size_t)row * DIM + 2 * p) = h;
        *(uint32_t*)(OL + (size_t)row * DIM + 2 * p) = l;
    }
}

// ======================= mma.sync flash attention =======================
#define AQB  128
#define ASTR 136
#define AQR  (AQB * ASTR)
#define ATL  (32 * ASTR)
#define ASTAGE (4 * ATL)
#define ANST 4
#define ATT_SMEM_BYTES ((2 * AQR + 3 * ASTAGE) * 2)   // stage 3 lives in Q region

__global__ __launch_bounds__(256)
void attn_mma(const __nv_bfloat16* __restrict__ Qh, const __nv_bfloat16* __restrict__ Ql,
              const __nv_bfloat16* __restrict__ Kh, const __nv_bfloat16* __restrict__ Kl,
              const __nv_bfloat16* __restrict__ Vh, const __nv_bfloat16* __restrict__ Vl,
              __nv_bfloat16* __restrict__ Oh, __nv_bfloat16* __restrict__ Ol) {
    extern __shared__ __nv_bfloat16 smb[];
    const uint32_t sbase = s2u(smb);
    const int head = blockIdx.y;
    const int q0   = blockIdx.x * AQB;
    const int v    = q0 / VS;
    const int col0 = head * HD;
    const int tid  = threadIdx.x;
    const int warp = tid >> 5, lane = tid & 31;

    const int f_lo = (q0 % VS) / TPF;
    const int f_hi = ((q0 + AQB - 1) % VS) / TPF;
    const int span = (f_hi != f_lo);
    const int fw   = ((q0 + warp * 16) % VS) / TPF;

    for (int i = tid; i < AQB * 16; i += 256) {
        int r = i >> 4, seg = i & 15;
        *(uint4*)&smb[r * ASTR + seg * 8] =
            *(const uint4*)&Qh[(size_t)(q0 + r) * DIM + col0 + seg * 8];
        *(uint4*)&smb[AQR + r * ASTR + seg * 8] =
            *(const uint4*)&Ql[(size_t)(q0 + r) * DIM + col0 + seg * 8];
    }

    const int baseA = v * VS;
    const int baseBv = (1 - v) * VS;
    const int NT = 56 + (span ? 28 : 14);

    const __nv_bfloat16* ptrs[4] = {Kh, Kl, Vh, Vl};

    auto tile_base = [&](int t) -> int {
        if (t < 56) return baseA + t * 32;
        int tt = t - 56;
        int fi = (tt < 14) ? f_lo : f_hi;
        int ttt = (tt < 14) ? tt : tt - 14;
        return baseBv + fi * TPF + ttt * 32;
    };

    auto stage_off = [&](int s) -> uint32_t {
        return (s == 3) ? 0u : (uint32_t)(2 * AQR + s * ASTAGE);
    };

    auto issue_tile = [&](int t, int s) {
        int kb = tile_base(t);
        uint32_t so = stage_off(s);
#pragma unroll
        for (int j = 0; j < 8; j++) {
            int i = tid + j * 256;
            int arr = i >> 9;
            int idx = i & 511;
            int r = idx >> 4, seg = idx & 15;
            const __nv_bfloat16* src = ptrs[arr] + (size_t)(kb + r) * DIM + col0 + seg * 8;
            uint32_t dst = sbase + (uint32_t)(so + arr * ATL + r * ASTR + seg * 8) * 2;
            cp16(dst, src);
        }
        cp_commit();
    };

    issue_tile(0, 0);
    issue_tile(1, 1);
    __syncthreads();

    const uint32_t q_aoff = (uint32_t)(warp * 16 + (lane & 15)) * (ASTR * 2)
                          + (uint32_t)((lane >> 4) * 16);
    uint32_t aQh[8][4], aQl[8][4];
#pragma unroll
    for (int ks = 0; ks < 8; ks++) {
        ldsm_x4(aQh[ks], sbase + q_aoff + ks * 32);
        ldsm_x4(aQl[ks], sbase + AQR * 2 + q_aoff + ks * 32);
    }

    float m[2] = {-1e30f, -1e30f};
    float l[2] = {0.f, 0.f};
    float acc[16][4];
#pragma unroll
    for (int nt = 0; nt < 16; nt++)
#pragma unroll
        for (int j = 0; j < 4; j++) acc[nt][j] = 0.f;

    const uint32_t k_bro  = (uint32_t)((lane & 7) + 8 * ((lane >> 4) & 1));
    const uint32_t k_bco  = (uint32_t)(((lane >> 3) & 1) * 16);
    const uint32_t v_row  = (uint32_t)(lane & 15);
    const uint32_t v_cofs = (uint32_t)(8 * ((lane >> 4) & 1));

    int s = 0;
    for (int t = 0; t < NT; t++) {
        if (t + 1 < NT) cp_wait<1>(); else cp_wait<0>();
        __syncthreads();
        if (t + 2 < NT) {
            int s2 = s + 2; if (s2 >= ANST) s2 -= ANST;
            issue_tile(t + 2, s2);
        }

        bool act = (t < 56) || (((t - 56) < 14 ? f_lo : f_hi) == fw);

        if (act) {
            const uint32_t st = sbase + stage_off(s) * 2;
            const uint32_t khb = st, klb = st + ATL * 2, vhb = st + 2 * ATL * 2, vlb = st + 3 * ATL * 2;

            float S[4][4];
#pragma unroll
            for (int nt = 0; nt < 4; nt++)
#pragma unroll
                for (int j = 0; j < 4; j++) S[nt][j] = 0.f;

#pragma unroll
            for (int ks = 0; ks < 8; ks++) {
                uint32_t bKh[8], bKl[8];
#pragma unroll
                for (int p = 0; p < 2; p++) {
                    uint32_t boff = (uint32_t)(p * 16 + k_bro) * (ASTR * 2) + ks * 32 + k_bco;
                    ldsm_x4(&bKh[4 * p], khb + boff);
                    ldsm_x4(&bKl[4 * p], klb + boff);
                }
#pragma unroll
                for (int nt = 0; nt < 4; nt++) {
                    mma16816(S[nt], aQh[ks], &bKh[2 * nt]);
                    mma16816(S[nt], aQh[ks], &bKl[2 * nt]);
                    mma16816(S[nt], aQl[ks], &bKh[2 * nt]);
                }
            }

            float mn[2], corr[2];
#pragma unroll
            for (int j = 0; j < 2; j++) {
                float mx = -1e30f;
#pragma unroll
                for (int nt = 0; nt < 4; nt++)
                    mx = fmaxf(mx, fmaxf(S[nt][2 * j], S[nt][2 * j + 1]));
                mx = fmaxf(mx, __shfl_xor_sync(~0u, mx, 1));
                mx = fmaxf(mx, __shfl_xor_sync(~0u, mx, 2));
                mn[j] = fmaxf(m[j], mx);
                corr[j] = __expf(m[j] - mn[j]);
            }
            bool resc = !__all_sync(~0u, (mn[0] == m[0]) && (mn[1] == m[1]));
            m[0] = mn[0]; m[1] = mn[1];

            uint32_t ph[4][2], pl[4][2];
#pragma unroll
            for (int j = 0; j < 2; j++) {
                float rs = 0.f;
#pragma unroll
                for (int nt = 0; nt < 4; nt++) {
                    float e0 = __expf(S[nt][2 * j]     - mn[j]);
                    float e1 = __expf(S[nt][2 * j + 1] - mn[j]);
                    S[nt][2 * j] = e0; S[nt][2 * j + 1] = e1;
                    rs += e0 + e1;
                }
                rs += __shfl_xor_sync(~0u, rs, 1);
                rs += __shfl_xor_sync(~0u, rs, 2);
                l[j] = l[j] * corr[j] + rs;
            }
            if (resc) {
#pragma unroll
                for (int nt = 0; nt < 16; nt++) {
                    acc[nt][0] *= corr[0]; acc[nt][1] *= corr[0];
                    acc[nt][2] *= corr[1]; acc[nt][3] *= corr[1];
                }
            }
#pragma unroll
            for (int nt = 0; nt < 4; nt++) {
#pragma unroll
                for (int j = 0; j < 2; j++) {
                    float e0 = S[nt][2 * j], e1 = S[nt][2 * j + 1];
                    uint32_t h = packbf(e0, e1);
                    __nv_bfloat162 H = *(__nv_bfloat162*)&h;
                    ph[nt][j] = h;
                    pl[nt][j] = packbf(e0 - __bfloat162float(H.x), e1 - __bfloat162float(H.y));
                }
            }

#pragma unroll
            for (int ks2 = 0; ks2 < 2; ks2++) {
                uint32_t aPh[4] = {ph[2 * ks2][0], ph[2 * ks2][1], ph[2 * ks2 + 1][0], ph[2 * ks2 + 1][1]};
                uint32_t aPl[4] = {pl[2 * ks2][0], pl[2 * ks2][1], pl[2 * ks2 + 1][0], pl[2 * ks2 + 1][1]};
#pragma unroll
                for (int dp = 0; dp < 8; dp++) {
                    uint32_t bVh[4], bVl[4];
                    uint32_t voff = (uint32_t)(ks2 * 16 + v_row) * (ASTR * 2)
                                  + (uint32_t)(dp * 16 + v_cofs) * 2;
                    ldsm_x4_t(bVh, vhb + voff);
                    mma16816(acc[2 * dp],     aPh, &bVh[0]);
                    mma16816(acc[2 * dp + 1], aPh, &bVh[2]);
                    mma16816(acc[2 * dp],     aPl, &bVh[0]);
                    mma16816(acc[2 * dp + 1], aPl, &bVh[2]);
                    ldsm_x4_t(bVl, vlb + voff);
                    mma16816(acc[2 * dp],     aPh, &bVl[0]);
                    mma16816(acc[2 * dp + 1], aPh, &bVl[2]);
                }
            }
        }
        if (++s == ANST) s = 0;
    }

#pragma unroll
    for (int j = 0; j < 2; j++) {
        float inv = 1.f / l[j];
        int row = q0 + warp * 16 + (lane >> 2) + 8 * j;
#pragma unroll
        for (int nt = 0; nt < 16; nt++) {
            float o0 = acc[nt][2 * j] * inv;
            float o1 = acc[nt][2 * j + 1] * inv;
            uint32_t h = packbf(o0, o1);
            __nv_bfloat162 H = *(__nv_bfloat162*)&h;
            uint32_t lo = packbf(o0 - __bfloat162float(H.x), o1 - __bfloat162float(H.y));
            size_t off = (size_t)row * DIM + col0 + nt * 8 + 2 * (lane & 3);
            *(uint32_t*)(Oh + off) = h;
            *(uint32_t*)(Ol + off) = lo;
        }
    }
}

// ======================= launch =======================
extern "C" void kernel_launch(void* const* d_in, const int* in_sizes, int n_in,
                              void* d_out, int out_size) {
    const float* x     = (const float*)d_in[0];
    const float* freqs = (const float*)d_in[1];
    const float* q_w   = (const float*)d_in[2];
    const float* q_b   = (const float*)d_in[3];
    const float* k_w   = (const float*)d_in[4];
    const float* k_b   = (const float*)d_in[5];
    const float* v_w   = (const float*)d_in[6];
    const float* v_b   = (const float*)d_in[7];
    const float* o_w   = (const float*)d_in[8];
    const float* o_b   = (const float*)d_in[9];
    const float* nqw   = (const float*)d_in[10];
    const float* nkw   = (const float*)d_in[11];

    float *gq, *gk;
    __nv_bfloat16 *xh, *xl, *qh, *ql, *kh, *kl, *vh, *vl, *oh, *ol, *wh, *wl;
    cudaGetSymbolAddress((void**)&gq, g_q);
    cudaGetSymbolAddress((void**)&gk, g_k);
    cudaGetSymbolAddress((void**)&xh, g_xh);
    cudaGetSymbolAddress((void**)&xl, g_xl);
    cudaGetSymbolAddress((void**)&qh, g_qh);
    cudaGetSymbolAddress((void**)&ql, g_ql);
    cudaGetSymbolAddress((void**)&kh, g_kh);
    cudaGetSymbolAddress((void**)&kl, g_kl);
    cudaGetSymbolAddress((void**)&vh, g_vh);
    cudaGetSymbolAddress((void**)&vl, g_vl);
    cudaGetSymbolAddress((void**)&oh, g_oh);
    cudaGetSymbolAddress((void**)&ol, g_ol);
    cudaGetSymbolAddress((void**)&wh, g_wh);
    cudaGetSymbolAddress((void**)&wl, g_wl);

    const size_t WSZ = (size_t)DIM * DIM;
    __nv_bfloat16 *owh = wh + 3 * WSZ, *owl = wl + 3 * WSZ;

    split_all<<<dim3((NX4 + 255) / 256, 5), 256>>>(x, q_w, k_w, v_w, o_w, xh, xl, wh, wl);

    cudaFuncSetAttribute(gemm_qkv, cudaFuncAttributeMaxDynamicSharedMemorySize,
                         GEMM_SMEM_BYTES);
    cudaFuncSetAttribute(gemm_o, cudaFuncAttributeMaxDynamicSharedMemorySize,
                         GEMM_SMEM_BYTES);
    gemm_qkv<<<dim3(DIM / 128, TS / 128, 3), 256, GEMM_SMEM_BYTES>>>(
        xh, xl, wh, wl, q_b, k_b, v_b, gq, gk, vh, vl);

    norm_rope_kernel<<<dim3(TS, 2), 256>>>(gq, gk, freqs, nqw, nkw, qh, ql, kh, kl);

    cudaFuncSetAttribute(attn_mma, cudaFuncAttributeMaxDynamicSharedMemorySize,
                         ATT_SMEM_BYTES);
    attn_mma<<<dim3(TS / AQB, NH), 256, ATT_SMEM_BYTES>>>(qh, ql, kh, kl, vh, vl, oh, ol);

    gemm_o<<<dim3(DIM / 128, TS / 128), 256, GEMM_SMEM_BYTES>>>(
        oh, ol, owh, owl, o_b, (float*)d_out);
}

// round 11
// speedup vs baseline: 1.1036x; 1.0101x over previous
#include <cuda_runtime.h>
#include <cuda_bf16.h>
#include <cstdint>

#define TS   3584
#define DIM  1536
#define NH   12
#define HD   128
#define VS   1792
#define TPF  448
#define NW   28
#define EPS  1e-6f
#define SCALE 0.08838834764831845f   // 1/sqrt(128)

// -------- scratch (device globals; no allocations allowed) --------
__device__ float g_q[(size_t)TS * DIM];
__device__ float g_k[(size_t)TS * DIM];
__device__ __nv_bfloat16 g_xh[(size_t)TS * DIM];
__device__ __nv_bfloat16 g_xl[(size_t)TS * DIM];
__device__ __nv_bfloat16 g_qh[(size_t)TS * DIM];
__device__ __nv_bfloat16 g_ql[(size_t)TS * DIM];
__device__ __nv_bfloat16 g_kh[(size_t)TS * DIM];
__device__ __nv_bfloat16 g_kl[(size_t)TS * DIM];
__device__ __nv_bfloat16 g_vh[(size_t)TS * DIM];
__device__ __nv_bfloat16 g_vl[(size_t)TS * DIM];
__device__ __nv_bfloat16 g_oh[(size_t)TS * DIM];
__device__ __nv_bfloat16 g_ol[(size_t)TS * DIM];
__device__ __nv_bfloat16 g_wh[4][(size_t)DIM * DIM];
__device__ __nv_bfloat16 g_wl[4][(size_t)DIM * DIM];

// ======================= PTX helpers =======================
__device__ __forceinline__ uint32_t s2u(const void* p) {
    uint32_t a;
    asm("{ .reg .u64 t; cvta.to.shared.u64 t, %1; cvt.u32.u64 %0, t; }"
        : "=r"(a) : "l"(p));
    return a;
}
__device__ __forceinline__ void ldsm_x4(uint32_t* r, uint32_t addr) {
    asm volatile("ldmatrix.sync.aligned.m8n8.x4.shared.b16 {%0,%1,%2,%3}, [%4];"
                 : "=r"(r[0]), "=r"(r[1]), "=r"(r[2]), "=r"(r[3]) : "r"(addr));
}
__device__ __forceinline__ void ldsm_x4_t(uint32_t* r, uint32_t addr) {
    asm volatile("ldmatrix.sync.aligned.m8n8.x4.trans.shared.b16 {%0,%1,%2,%3}, [%4];"
                 : "=r"(r[0]), "=r"(r[1]), "=r"(r[2]), "=r"(r[3]) : "r"(addr));
}
__device__ __forceinline__ void mma16816(float* c, const uint32_t* a, const uint32_t* b) {
    asm volatile(
        "mma.sync.aligned.m16n8k16.row.col.f32.bf16.bf16.f32 "
        "{%0,%1,%2,%3}, {%4,%5,%6,%7}, {%8,%9}, {%0,%1,%2,%3};"
        : "+f"(c[0]), "+f"(c[1]), "+f"(c[2]), "+f"(c[3])
        : "r"(a[0]), "r"(a[1]), "r"(a[2]), "r"(a[3]), "r"(b[0]), "r"(b[1]));
}
__device__ __forceinline__ void cp16(uint32_t dst, const void* src) {
    asm volatile("cp.async.ca.shared.global [%0], [%1], 16;"
                 :: "r"(dst), "l"(src) : "memory");
}
__device__ __forceinline__ void cp_commit() {
    asm volatile("cp.async.commit_group;" ::: "memory");
}
template <int N>
__device__ __forceinline__ void cp_wait() {
    asm volatile("cp.async.wait_group %0;" :: "n"(N) : "memory");
}
__device__ __forceinline__ uint32_t packbf(float a, float b) {
    __nv_bfloat162 h;
    h.x = __float2bfloat16(a);
    h.y = __float2bfloat16(b);
    return *(uint32_t*)&h;
}

// ======================= fp32 -> (hi, lo) bf16 split (fused) ================
__device__ __forceinline__ void split_one(const float* __restrict__ in,
                                          __nv_bfloat16* __restrict__ hi,
                                          __nv_bfloat16* __restrict__ lo, int i) {
    float4 v = ((const float4*)in)[i];
    __nv_bfloat16 h0 = __float2bfloat16(v.x);
    __nv_bfloat16 h1 = __float2bfloat16(v.y);
    __nv_bfloat16 h2 = __float2bfloat16(v.z);
    __nv_bfloat16 h3 = __float2bfloat16(v.w);
    __nv_bfloat162 H0, H1, L0, L1;
    H0.x = h0; H0.y = h1; H1.x = h2; H1.y = h3;
    L0.x = __float2bfloat16(v.x - __bfloat162float(h0));
    L0.y = __float2bfloat16(v.y - __bfloat162float(h1));
    L1.x = __float2bfloat16(v.z - __bfloat162float(h2));
    L1.y = __float2bfloat16(v.w - __bfloat162float(h3));
    ((__nv_bfloat162*)hi)[2 * i]     = H0;
    ((__nv_bfloat162*)hi)[2 * i + 1] = H1;
    ((__nv_bfloat162*)lo)[2 * i]     = L0;
    ((__nv_bfloat162*)lo)[2 * i + 1] = L1;
}

#define NX4 (TS * DIM / 4)
#define NW4 (DIM * DIM / 4)

__global__ __launch_bounds__(256)
void split_all(const float* __restrict__ x,
               const float* __restrict__ qw, const float* __restrict__ kw,
               const float* __restrict__ vw, const float* __restrict__ ow,
               __nv_bfloat16* __restrict__ xh, __nv_bfloat16* __restrict__ xl,
               __nv_bfloat16* __restrict__ wh, __nv_bfloat16* __restrict__ wl) {
    int i = blockIdx.x * 256 + threadIdx.x;
    int z = blockIdx.y;
    if (z == 0) {
        if (i < NX4) split_one(x, xh, xl, i);
    } else {
        if (i < NW4) {
            const float* in = (z == 1) ? qw : (z == 2) ? kw : (z == 3) ? vw : ow;
            split_one(in, wh + (size_t)(z - 1) * DIM * DIM,
                          wl + (size_t)(z - 1) * DIM * DIM, i);
        }
    }
}

// ======================= mma.sync split-bf16 GEMM core ======================
// 256 threads, 8 warps (2M x 4N, 64x32 per warp), 2-stage cp.async ring.
// SSTR=40 (80B rows). 80KB smem -> 2 CTAs/SM.  (R10 WIN configuration)
#define SSTR 40
#define TILE_E (128 * SSTR)
#define TILE_B (TILE_E * 2)
#define BUF_E  (4 * TILE_E)
#define GNST 2
#define GEMM_SMEM_BYTES (GNST * BUF_E * 2)   // 81920

struct GemmOut {
    float acc[4][4][4];
};

__device__ __forceinline__ void gemm_core(
    const __nv_bfloat16* __restrict__ Ah, const __nv_bfloat16* __restrict__ Al,
    const __nv_bfloat16* __restrict__ Wh, const __nv_bfloat16* __restrict__ Wl,
    int m0, int n0, int K, __nv_bfloat16* sm, GemmOut& out) {
    const int tid  = threadIdx.x;
    const int warp = tid >> 5, lane = tid & 31;
    const int wm   = warp & 1;
    const int wn   = warp >> 1;
    const uint32_t sbase = s2u(sm);

#pragma unroll
    for (int i = 0; i < 4; i++)
#pragma unroll
        for (int j = 0; j < 4; j++)
#pragma unroll
            for (int k = 0; k < 4; k++) out.acc[i][j][k] = 0.f;

    const __nv_bfloat16* srcs[4] = {Ah, Al, Wh, Wl};

    auto issue_chunk = [&](int c, int s) {
#pragma unroll
        for (int j = 0; j < 8; j++) {
            int i = tid + j * 256;
            int arr = i >> 9;
            int idx = i & 511;
            int row = idx >> 2, seg = idx & 3;
            const __nv_bfloat16* src = srcs[arr] +
                (size_t)((arr < 2 ? m0 : n0) + row) * K + c * 32 + seg * 8;
            uint32_t dst = sbase + (uint32_t)(s * BUF_E + arr * TILE_E + row * SSTR + seg * 8) * 2;
            cp16(dst, src);
        }
        cp_commit();
    };

    const int NC = K / 32;
    issue_chunk(0, 0);

    const uint32_t arow = (uint32_t)(wm * 64 + (lane & 15));
    const uint32_t acol = (uint32_t)((lane >> 4) * 16);
    const uint32_t bro  = (uint32_t)((lane & 7) + 8 * ((lane >> 4) & 1));
    const uint32_t bco  = (uint32_t)(((lane >> 3) & 1) * 16);

    for (int c = 0; c < NC; c++) {
        cp_wait<0>();
        __syncthreads();
        if (c + 1 < NC) issue_chunk(c + 1, (c + 1) & 1);
        const uint32_t bb = sbase + (uint32_t)((c & 1) * BUF_E) * 2;
#pragma unroll
        for (int ks = 0; ks < 2; ks++) {
            uint32_t aH[4][4], aL[4][4], bH[8], bL[8];
            const uint32_t aoff = arow * (SSTR * 2) + ks * 32 + acol;
#pragma unroll
            for (int mt = 0; mt < 4; mt++)
                ldsm_x4(aH[mt], bb + 0 * TILE_B + aoff + mt * 16 * (SSTR * 2));
#pragma unroll
            for (int p = 0; p < 2; p++) {
                uint32_t boff = (uint32_t)(wn * 32 + p * 16 + bro) * (SSTR * 2) + ks * 32 + bco;
                ldsm_x4(&bH[4 * p], bb + 2 * TILE_B + boff);
            }
#pragma unroll
            for (int mt = 0; mt < 4; mt++)
#pragma unroll
                for (int nt = 0; nt < 4; nt++)
                    mma16816(out.acc[mt][nt], aH[mt], &bH[2 * nt]);
#pragma unroll
            for (int mt = 0; mt < 4; mt++)
                ldsm_x4(aL[mt], bb + 1 * TILE_B + aoff + mt * 16 * (SSTR * 2));
#pragma unroll
            for (int mt = 0; mt < 4; mt++)
#pragma unroll
                for (int nt = 0; nt < 4; nt++)
                    mma16816(out.acc[mt][nt], aL[mt], &bH[2 * nt]);
#pragma unroll
            for (int p = 0; p < 2; p++) {
                uint32_t boff = (uint32_t)(wn * 32 + p * 16 + bro) * (SSTR * 2) + ks * 32 + bco;
                ldsm_x4(&bL[4 * p], bb + 3 * TILE_B + boff);
            }
#pragma unroll
            for (int mt = 0; mt < 4; mt++)
#pragma unroll
                for (int nt = 0; nt < 4; nt++)
                    mma16816(out.acc[mt][nt], aH[mt], &bL[2 * nt]);
        }
    }
}

// ---- fused QKV projection: z = 0 (Q, f32) / 1 (K, f32) / 2 (V, bf16 hi/lo) ----
__global__ __launch_bounds__(256, 2)
void gemm_qkv(const __nv_bfloat16* __restrict__ xh, const __nv_bfloat16* __restrict__ xl,
              const __nv_bfloat16* __restrict__ whb, const __nv_bfloat16* __restrict__ wlb,
              const float* __restrict__ qb, const float* __restrict__ kb,
              const float* __restrict__ vb,
              float* __restrict__ gq, float* __restrict__ gk,
              __nv_bfloat16* __restrict__ vh, __nv_bfloat16* __restrict__ vl) {
    extern __shared__ __nv_bfloat16 sm[];
    const int z  = blockIdx.z;
    const int m0 = blockIdx.y * 128, n0 = blockIdx.x * 128;
    const size_t WSZ = (size_t)DIM * DIM;
    const __nv_bfloat16* Wh = whb + (size_t)z * WSZ;
    const __nv_bfloat16* Wl = wlb + (size_t)z * WSZ;
    const float* bias = (z == 0) ? qb : (z == 1) ? kb : vb;

    GemmOut out;
    gemm_core(xh, xl, Wh, Wl, m0, n0, DIM, sm, out);

    const int warp = threadIdx.x >> 5, lane = threadIdx.x & 31;
    const int row_base = m0 + (warp & 1) * 64 + (lane >> 2);
    const int col_base = n0 + (warp >> 1) * 32 + (lane & 3) * 2;
    float* Cf = (z == 0) ? gq : gk;
#pragma unroll
    for (int mt = 0; mt < 4; mt++) {
#pragma unroll
        for (int nt = 0; nt < 4; nt++) {
            int r = row_base + mt * 16;
            int cc = col_base + nt * 8;
            float bx = bias[cc], by = bias[cc + 1];
            float v00 = out.acc[mt][nt][0] + bx, v01 = out.acc[mt][nt][1] + by;
            float v10 = out.acc[mt][nt][2] + bx, v11 = out.acc[mt][nt][3] + by;
            if (z < 2) {
                *(float2*)(Cf + (size_t)r * DIM + cc)       = make_float2(v00, v01);
                *(float2*)(Cf + (size_t)(r + 8) * DIM + cc) = make_float2(v10, v11);
            } else {
                uint32_t h0 = packbf(v00, v01);
                uint32_t h1 = packbf(v10, v11);
                __nv_bfloat162 H0 = *(__nv_bfloat162*)&h0;
                __nv_bfloat162 H1 = *(__nv_bfloat162*)&h1;
                uint32_t l0 = packbf(v00 - __bfloat162float(H0.x), v01 - __bfloat162float(H0.y));
                uint32_t l1 = packbf(v10 - __bfloat162float(H1.x), v11 - __bfloat162float(H1.y));
                *(uint32_t*)(vh + (size_t)r * DIM + cc)       = h0;
                *(uint32_t*)(vh + (size_t)(r + 8) * DIM + cc) = h1;
                *(uint32_t*)(vl + (size_t)r * DIM + cc)       = l0;
                *(uint32_t*)(vl + (size_t)(r + 8) * DIM + cc) = l1;
            }
        }
    }
}

// ---- O projection (f32 out) ----
__global__ __launch_bounds__(256, 2)
void gemm_o(const __nv_bfloat16* __restrict__ Ah, const __nv_bfloat16* __restrict__ Al,
            const __nv_bfloat16* __restrict__ Wh, const __nv_bfloat16* __restrict__ Wl,
            const float* __restrict__ bias, float* __restrict__ Cf) {
    extern __shared__ __nv_bfloat16 sm[];
    const int m0 = blockIdx.y * 128, n0 = blockIdx.x * 128;
    GemmOut out;
    gemm_core(Ah, Al, Wh, Wl, m0, n0, DIM, sm, out);

    const int warp = threadIdx.x >> 5, lane = threadIdx.x & 31;
    const int row_base = m0 + (warp & 1) * 64 + (lane >> 2);
    const int col_base = n0 + (warp >> 1) * 32 + (lane & 3) * 2;
#pragma unroll
    for (int mt = 0; mt < 4; mt++) {
#pragma unroll
        for (int nt = 0; nt < 4; nt++) {
            int r = row_base + mt * 16;
            int cc = col_base + nt * 8;
            float bx = bias[cc], by = bias[cc + 1];
            *(float2*)(Cf + (size_t)r * DIM + cc) =
                make_float2(out.acc[mt][nt][0] + bx, out.acc[mt][nt][1] + by);
            *(float2*)(Cf + (size_t)(r + 8) * DIM + cc) =
                make_float2(out.acc[mt][nt][2] + bx, out.acc[mt][nt][3] + by);
        }
    }
}

// ======================= RMSNorm + RoPE -> bf16 hi/lo =======================
__global__ __launch_bounds__(256)
void norm_rope_kernel(const float* __restrict__ q, const float* __restrict__ k,
                      const float* __restrict__ freqs,
                      const float* __restrict__ nqw, const float* __restrict__ nkw,
                      __nv_bfloat16* __restrict__ QH, __nv_bfloat16* __restrict__ QL,
                      __nv_bfloat16* __restrict__ KH, __nv_bfloat16* __restrict__ KL) {
    const int row = blockIdx.x;
    const float* x = (blockIdx.y == 0 ? q : k) + (size_t)row * DIM;
    const float* w = (blockIdx.y == 0) ? nqw : nkw;
    __nv_bfloat16* OH = (blockIdx.y == 0) ? QH : KH;
    __nv_bfloat16* OL = (blockIdx.y == 0) ? QL : KL;
    const float sc = (blockIdx.y == 0) ? SCALE : 1.f;
    const int tid = threadIdx.x;

    float ss = 0.f;
    for (int i = tid; i < DIM; i += 256) { float v = x[i]; ss += v * v; }
#pragma unroll
    for (int o = 16; o > 0; o >>= 1) ss += __shfl_xor_sync(~0u, ss, o);
    __shared__ float warpsum[8];
    if ((tid & 31) == 0) warpsum[tid >> 5] = ss;
    __syncthreads();
    float tot = 0.f;
#pragma unroll
    for (int i = 0; i < 8; i++) tot += warpsum[i];
    const float rs = rsqrtf(tot / (float)DIM + EPS);

    const int tv = row % VS;
    const int f  = tv / TPF;
    const int r  = tv % TPF;
    const int hh = r / NW;
    const int ww = r % NW;

    for (int p = tid; p < DIM / 2; p += 256) {
        int c = p & 63;
        int idx = (c < 22) ? f : ((c < 43) ? hh : ww);
        float ang = freqs[idx * 64 + c];
        float sn, cs;
        sincosf(ang, &sn, &cs);
        float x0 = x[2 * p]     * rs * w[2 * p];
        float x1 = x[2 * p + 1] * rs * w[2 * p + 1];
        float r0 = (x0 * cs - x1 * sn) * sc;
        float r1 = (x0 * sn + x1 * cs) * sc;
        uint32_t h = packbf(r0, r1);
        __nv_bfloat162 H = *(__nv_bfloat162*)&h;
        uint32_t l = packbf(r0 - __bfloat162float(H.x), r1 - __bfloat162float(H.y));
        *(uint32_t*)(OH + (size_t)row * DIM + 2 * p) = h;
        *(uint32_t*)(OL + (size_t)row * DIM + 2 * p) = l;
    }
}

// ======================= mma.sync flash attention (key-split warp pairs) ====
// 64 queries x 1 head per block, 8 warps = 4 row-groups x 2 key-halves.
// Each warp: 16 rows x 16-key half per 32-key tile, private (m,l,acc);
// one logsumexp merge per warp pair at the end. 2-stage cp.async ring.
// Smem 102KB + regs <=128 -> 2 CTAs/SM (16 warps).
#define AQB  64
#define ASTR 136
#define AQR  (AQB * ASTR)          // 8704 elems
#define ATL  (32 * ASTR)           // 4352 elems
#define ASTAGE (4 * ATL)           // 17408 elems (34816 B)
#define ATT_SMEM_BYTES ((2 * AQR + 2 * ASTAGE) * 2)   // 104448

__global__ __launch_bounds__(256, 2)
void attn_mma(const __nv_bfloat16* __restrict__ Qh, const __nv_bfloat16* __restrict__ Ql,
              const __nv_bfloat16* __restrict__ Kh, const __nv_bfloat16* __restrict__ Kl,
              const __nv_bfloat16* __restrict__ Vh, const __nv_bfloat16* __restrict__ Vl,
              __nv_bfloat16* __restrict__ Oh, __nv_bfloat16* __restrict__ Ol) {
    extern __shared__ __nv_bfloat16 smb[];
    const uint32_t sbase = s2u(smb);
    const int head = blockIdx.y;
    const int q0   = blockIdx.x * AQB;
    const int v    = q0 / VS;
    const int f    = (q0 % VS) / TPF;      // uniform: 64 | 448
    const int col0 = head * HD;
    const int tid  = threadIdx.x;
    const int warp = tid >> 5, lane = tid & 31;
    const int g    = warp >> 1;            // row group (0..3), 16 rows each
    const int h    = warp & 1;             // key half (0..1), 16 keys each

    // ---- load Q tiles (hi/lo) into smem ----
    for (int i = tid; i < AQB * 16; i += 256) {
        int r = i >> 4, seg = i & 15;
        *(uint4*)&smb[r * ASTR + seg * 8] =
            *(const uint4*)&Qh[(size_t)(q0 + r) * DIM + col0 + seg * 8];
        *(uint4*)&smb[AQR + r * ASTR + seg * 8] =
            *(const uint4*)&Ql[(size_t)(q0 + r) * DIM + col0 + seg * 8];
    }

    const int baseA = v * VS;
    const int baseB = (1 - v) * VS + f * TPF;
    const int NT = 70;   // 56 same-view + 14 cross-view tiles

    const __nv_bfloat16* ptrs[4] = {Kh, Kl, Vh, Vl};

    auto issue_tile = [&](int t, int s) {
        int kb = (t < 56) ? (baseA + t * 32) : (baseB + (t - 56) * 32);
#pragma unroll
        for (int j = 0; j < 8; j++) {
            int i = tid + j * 256;
            int arr = i >> 9;
            int idx = i & 511;
            int r = idx >> 4, seg = idx & 15;
            const __nv_bfloat16* src = ptrs[arr] + (size_t)(kb + r) * DIM + col0 + seg * 8;
            uint32_t dst = sbase + (uint32_t)(2 * AQR + s * ASTAGE + arr * ATL + r * ASTR + seg * 8) * 2;
            cp16(dst, src);
        }
        cp_commit();
    };

    issue_tile(0, 0);

    float m[2] = {-1e30f, -1e30f};
    float l[2] = {0.f, 0.f};
    float acc[16][4];
#pragma unroll
    for (int nt = 0; nt < 16; nt++)
#pragma unroll
        for (int j = 0; j < 4; j++) acc[nt][j] = 0.f;

    const uint32_t q_goff = (uint32_t)(g * 16 + (lane & 15)) * (ASTR * 2)
                          + (uint32_t)((lane >> 4) * 16);
    const uint32_t k_bro  = (uint32_t)(h * 16 + (lane & 7) + 8 * ((lane >> 4) & 1));
    const uint32_t k_bco  = (uint32_t)(((lane >> 3) & 1) * 16);
    const uint32_t v_row  = (uint32_t)(h * 16 + (lane & 15));
    const uint32_t v_cofs = (uint32_t)(8 * ((lane >> 4) & 1));

    for (int t = 0; t < NT; t++) {
        cp_wait<0>();
        __syncthreads();
        if (t + 1 < NT) issue_tile(t + 1, (t + 1) & 1);

        const uint32_t st = sbase + (uint32_t)(2 * AQR + (t & 1) * ASTAGE) * 2;
        const uint32_t khb = st, klb = st + ATL * 2, vhb = st + 2 * ATL * 2, vlb = st + 3 * ATL * 2;

        // ---- S = Q K^T over this warp's 16-key half (3 split terms) ----
        float S[2][4];
#pragma unroll
        for (int nt = 0; nt < 2; nt++)
#pragma unroll
            for (int j = 0; j < 4; j++) S[nt][j] = 0.f;

#pragma unroll
        for (int ks = 0; ks < 8; ks++) {
            uint32_t aQh[4], aQl[4], bKh[4], bKl[4];
            ldsm_x4(aQh, sbase + q_goff + ks * 32);
            ldsm_x4(aQl, sbase + AQR * 2 + q_goff + ks * 32);
            uint32_t boff = k_bro * (ASTR * 2) + ks * 32 + k_bco;
            ldsm_x4(bKh, khb + boff);
            ldsm_x4(bKl, klb + boff);
#pragma unroll
            for (int nt = 0; nt < 2; nt++) {
                mma16816(S[nt], aQh, &bKh[2 * nt]);
                mma16816(S[nt], aQh, &bKl[2 * nt]);
                mma16816(S[nt], aQl, &bKh[2 * nt]);
            }
        }

        // ---- online softmax over this warp's keys ----
        float mn[2], corr[2];
#pragma unroll
        for (int j = 0; j < 2; j++) {
            float mx = fmaxf(fmaxf(S[0][2 * j], S[0][2 * j + 1]),
                             fmaxf(S[1][2 * j], S[1][2 * j + 1]));
            mx = fmaxf(mx, __shfl_xor_sync(~0u, mx, 1));
            mx = fmaxf(mx, __shfl_xor_sync(~0u, mx, 2));
            mn[j] = fmaxf(m[j], mx);
            corr[j] = __expf(m[j] - mn[j]);
        }
        bool resc = !__all_sync(~0u, (mn[0] == m[0]) && (mn[1] == m[1]));
        m[0] = mn[0]; m[1] = mn[1];

        uint32_t ph[2][2], pl[2][2];
#pragma unroll
        for (int j = 0; j < 2; j++) {
            float rs = 0.f;
#pragma unroll
            for (int nt = 0; nt < 2; nt++) {
                float e0 = __expf(S[nt][2 * j]     - mn[j]);
                float e1 = __expf(S[nt][2 * j + 1] - mn[j]);
                S[nt][2 * j] = e0; S[nt][2 * j + 1] = e1;
                rs += e0 + e1;
            }
            rs += __shfl_xor_sync(~0u, rs, 1);
            rs += __shfl_xor_sync(~0u, rs, 2);
            l[j] = l[j] * corr[j] + rs;
        }
        if (resc) {
#pragma unroll
            for (int nt = 0; nt < 16; nt++) {
                acc[nt][0] *= corr[0]; acc[nt][1] *= corr[0];
                acc[nt][2] *= corr[1]; acc[nt][3] *= corr[1];
            }
        }
#pragma unroll
        for (int nt = 0; nt < 2; nt++) {
#pragma unroll
            for (int j = 0; j < 2; j++) {
                float e0 = S[nt][2 * j], e1 = S[nt][2 * j + 1];
                uint32_t hh = packbf(e0, e1);
                __nv_bfloat162 H = *(__nv_bfloat162*)&hh;
                ph[nt][j] = hh;
                pl[nt][j] = packbf(e0 - __bfloat162float(H.x), e1 - __bfloat162float(H.y));
            }
        }

        // ---- out += P V over this warp's keys (3 split terms) ----
        uint32_t aPh[4] = {ph[0][0], ph[0][1], ph[1][0], ph[1][1]};
        uint32_t aPl[4] = {pl[0][0], pl[0][1], pl[1][0], pl[1][1]};
#pragma unroll
        for (int dp = 0; dp < 8; dp++) {
            uint32_t bVh[4], bVl[4];
            uint32_t voff = v_row * (ASTR * 2) + (uint32_t)(dp * 16 + v_cofs) * 2;
            ldsm_x4_t(bVh, vhb + voff);
            mma16816(acc[2 * dp],     aPh, &bVh[0]);
            mma16816(acc[2 * dp + 1], aPh, &bVh[2]);
            mma16816(acc[2 * dp],     aPl, &bVh[0]);
            mma16816(acc[2 * dp + 1], aPl, &bVh[2]);
            ldsm_x4_t(bVl, vlb + voff);
            mma16816(acc[2 * dp],     aPh, &bVl[0]);
            mma16816(acc[2 * dp + 1], aPh, &bVl[2]);
        }
    }

    // ---- merge warp pairs (h=1 publishes, h=0 combines) ----
    __syncthreads();          // all tiles done; stage smem reusable
    float* ex = (float*)smb;  // 4 groups x 32 lanes x 68 floats = 34816 B
    if (h == 1) {
        float* d = ex + (g * 32 + lane) * 68;
        d[0] = m[0]; d[1] = m[1]; d[2] = l[0]; d[3] = l[1];
#pragma unroll
        for (int nt = 0; nt < 16; nt++) {
            d[4 + 4 * nt + 0] = acc[nt][0];
            d[4 + 4 * nt + 1] = acc[nt][1];
            d[4 + 4 * nt + 2] = acc[nt][2];
            d[4 + 4 * nt + 3] = acc[nt][3];
        }
    }
    __syncthreads();
    if (h == 0) {
        const float* d = ex + (g * 32 + lane) * 68;
        float pm[2] = {d[0], d[1]};
        float pll[2] = {d[2], d[3]};
        float a[2], b[2], inv[2];
#pragma unroll
        for (int j = 0; j < 2; j++) {
            float M = fmaxf(m[j], pm[j]);
            a[j] = __expf(m[j] - M);
            b[j] = __expf(pm[j] - M);
            inv[j] = 1.f / (a[j] * l[j] + b[j] * pll[j]);
        }
#pragma unroll
        for (int j = 0; j < 2; j++) {
            int row = q0 + g * 16 + (lane >> 2) + 8 * j;
#pragma unroll
            for (int nt = 0; nt < 16; nt++) {
                float o0 = (a[j] * acc[nt][2 * j]     + b[j] * d[4 + 4 * nt + 2 * j])     * inv[j];
                float o1 = (a[j] * acc[nt][2 * j + 1] + b[j] * d[4 + 4 * nt + 2 * j + 1]) * inv[j];
                uint32_t hh = packbf(o0, o1);
                __nv_bfloat162 H = *(__nv_bfloat162*)&hh;
                uint32_t lo = packbf(o0 - __bfloat162float(H.x), o1 - __bfloat162float(H.y));
                size_t off = (size_t)row * DIM + col0 + nt * 8 + 2 * (lane & 3);
                *(uint32_t*)(Oh + off) = hh;
                *(uint32_t*)(Ol + off) = lo;
            }
        }
    }
}

// ======================= launch =======================
extern "C" void kernel_launch(void* const* d_in, const int* in_sizes, int n_in,
                              void* d_out, int out_size) {
    const float* x     = (const float*)d_in[0];
    const float* freqs = (const float*)d_in[1];
    const float* q_w   = (const float*)d_in[2];
    const float* q_b   = (const float*)d_in[3];
    const float* k_w   = (const float*)d_in[4];
    const float* k_b   = (const float*)d_in[5];
    const float* v_w   = (const float*)d_in[6];
    const float* v_b   = (const float*)d_in[7];
    const float* o_w   = (const float*)d_in[8];
    const float* o_b   = (const float*)d_in[9];
    const float* nqw   = (const float*)d_in[10];
    const float* nkw   = (const float*)d_in[11];

    float *gq, *gk;
    __nv_bfloat16 *xh, *xl, *qh, *ql, *kh, *kl, *vh, *vl, *oh, *ol, *wh, *wl;
    cudaGetSymbolAddress((void**)&gq, g_q);
    cudaGetSymbolAddress((void**)&gk, g_k);
    cudaGetSymbolAddress((void**)&xh, g_xh);
    cudaGetSymbolAddress((void**)&xl, g_xl);
    cudaGetSymbolAddress((void**)&qh, g_qh);
    cudaGetSymbolAddress((void**)&ql, g_ql);
    cudaGetSymbolAddress((void**)&kh, g_kh);
    cudaGetSymbolAddress((void**)&kl, g_kl);
    cudaGetSymbolAddress((void**)&vh, g_vh);
    cudaGetSymbolAddress((void**)&vl, g_vl);
    cudaGetSymbolAddress((void**)&oh, g_oh);
    cudaGetSymbolAddress((void**)&ol, g_ol);
    cudaGetSymbolAddress((void**)&wh, g_wh);
    cudaGetSymbolAddress((void**)&wl, g_wl);

    const size_t WSZ = (size_t)DIM * DIM;
    __nv_bfloat16 *owh = wh + 3 * WSZ, *owl = wl + 3 * WSZ;

    split_all<<<dim3((NX4 + 255) / 256, 5), 256>>>(x, q_w, k_w, v_w, o_w, xh, xl, wh, wl);

    cudaFuncSetAttribute(gemm_qkv, cudaFuncAttributeMaxDynamicSharedMemorySize,
                         GEMM_SMEM_BYTES);
    cudaFuncSetAttribute(gemm_o, cudaFuncAttributeMaxDynamicSharedMemorySize,
                         GEMM_SMEM_BYTES);
    gemm_qkv<<<dim3(DIM / 128, TS / 128, 3), 256, GEMM_SMEM_BYTES>>>(
        xh, xl, wh, wl, q_b, k_b, v_b, gq, gk, vh, vl);

    norm_rope_kernel<<<dim3(TS, 2), 256>>>(gq, gk, freqs, nqw, nkw, qh, ql, kh, kl);

    cudaFuncSetAttribute(attn_mma, cudaFuncAttributeMaxDynamicSharedMemorySize,
                         ATT_SMEM_BYTES);
    attn_mma<<<dim3(TS / AQB, NH), 256, ATT_SMEM_BYTES>>>(qh, ql, kh, kl, vh, vl, oh, ol);

    gemm_o<<<dim3(DIM / 128, TS / 128), 256, GEMM_SMEM_BYTES>>>(
        oh, ol, owh, owl, o_b, (float*)d_out);
}